// round 11
// baseline (speedup 1.0000x reference)
#include <cuda_runtime.h>
#include <cuda_bf16.h>
#include <cuda_fp16.h>
#include <math.h>
#include <stdint.h>

#define S_LEN 2048
#define DIM 1024
#define NH 16
#define KVH 4
#define HD 64
#define NTOT 1792

__device__ float g_qkvg[S_LEN * NTOT];
__device__ float2 g_rot[S_LEN * 32];
__device__ __half g_xh[S_LEN * DIM];
__device__ __half g_wh[NTOT * DIM];
__device__ __half g_woh[DIM * DIM];
__device__ __half g_yh[S_LEN * DIM];
// attention operands, single fp16, layout [(head*2+half)][seq][32]
__device__ __half g_aq[NH*2*S_LEN*32];
__device__ __half g_ak[KVH*2*S_LEN*32];
__device__ __half g_av[KVH*2*S_LEN*32];

__device__ __forceinline__ uint32_t smem_u32(const void* p) {
    uint32_t a;
    asm("{ .reg .u64 t; cvta.to.shared.u64 t, %1; cvt.u32.u64 %0, t; }" : "=r"(a) : "l"(p));
    return a;
}
#define CP16(sm, gp) asm volatile("cp.async.cg.shared.global [%0], [%1], 16;" :: "r"(sm), "l"(gp))
#define LDSM4(r, addr) \
    asm volatile("ldmatrix.sync.aligned.m8n8.x4.shared.b16 {%0,%1,%2,%3}, [%4];" \
        : "=r"((r)[0]), "=r"((r)[1]), "=r"((r)[2]), "=r"((r)[3]) : "r"(addr))
#define LDSM4T(r, addr) \
    asm volatile("ldmatrix.sync.aligned.m8n8.x4.trans.shared.b16 {%0,%1,%2,%3}, [%4];" \
        : "=r"((r)[0]), "=r"((r)[1]), "=r"((r)[2]), "=r"((r)[3]) : "r"(addr))
#define MMAF16(d, a, b0, b1) \
    asm volatile("mma.sync.aligned.m16n8k16.row.col.f32.f16.f16.f32 " \
        "{%0,%1,%2,%3}, {%4,%5,%6,%7}, {%8,%9}, {%0,%1,%2,%3};" \
        : "+f"((d)[0]), "+f"((d)[1]), "+f"((d)[2]), "+f"((d)[3]) \
        : "r"((a)[0]), "r"((a)[1]), "r"((a)[2]), "r"((a)[3]), "r"(b0), "r"(b1))
#define PACKF16(r, a, b) asm("cvt.rn.f16x2.f32 %0, %1, %2;" : "=r"(r) : "f"(b), "f"(a))
#define EX2(d, x) asm("ex2.approx.ftz.f32 %0, %1;" : "=f"(d) : "f"(x))

// -------- fused fp32 -> fp16 conversion for all 6 tensors + rotary table ----
__global__ __launch_bounds__(256) void conv_all(
    const float* __restrict__ x,  const float* __restrict__ Wq,
    const float* __restrict__ Wk, const float* __restrict__ Wv,
    const float* __restrict__ Wg, const float* __restrict__ Wo)
{
    if (blockIdx.x >= 4864) {                       // rotary-table tail blocks
        const int i = (blockIdx.x - 4864) * 256 + threadIdx.x;   // < 65536
        const int m = i >> 5, t = i & 31;
        const float angle = ((float)(2 * t) / 64.0f) * 3.14159274101257324f;
        const float ang = (float)m * angle;
        double a = (double)ang;
        a -= rint(a * 0.15915494309189535) * 6.283185307179586;
        float c, sn;
        sincosf((float)a, &sn, &c);
        const float radius = 1.0f / (1.0f + (float)m * 0.01f);
        g_rot[i] = make_float2(c * radius, sn * radius);
        return;
    }
    const int i = blockIdx.x * 256 + threadIdx.x;
    const float* s; __half* d;
    if (i < 524288)      { size_t j = (size_t)i * 4;            s = x  + j; d = g_xh + j; }
    else if (i < 786432) { size_t j = (size_t)(i - 524288) * 4; s = Wq + j; d = g_wh + j; }
    else if (i < 851968) { size_t j = (size_t)(i - 786432) * 4; s = Wk + j; d = g_wh + 1048576 + j; }
    else if (i < 917504) { size_t j = (size_t)(i - 851968) * 4; s = Wv + j; d = g_wh + 1310720 + j; }
    else if (i < 983040) { size_t j = (size_t)(i - 917504) * 4; s = Wg + j; d = g_wh + 1572864 + j; }
    else                 { size_t j = (size_t)(i - 983040) * 4; s = Wo + j; d = g_woh + j; }
    float4 v = *(const float4*)s;
    __half2 h0 = __floats2half2_rn(v.x, v.y);
    __half2 h1 = __floats2half2_rn(v.z, v.w);
    *(__half2*)d = h0; *(__half2*)(d + 2) = h1;
}

// -------- fp16 HMMA GEMM: C[M,N] = A[M,K] @ B[N,K]^T, 3-stage --------
#define AST   18432
#define STG_B (2 * AST)
#define GSMEM (3 * STG_B)           // 110592

__device__ __forceinline__ void g_load_stage(
    uint32_t sb, const char* pA, const char* pB, int t, int s)
{
    const size_t gk = (size_t)s * 128;
    #pragma unroll
    for (int j = 0; j < 8; j++) {
        const int idx = t + 256 * j;
        const int arr = idx >> 10, rem = idx & 1023;
        const int row = rem >> 3, kc = rem & 7;
        const size_t go = (size_t)row * 2048 + gk + kc * 16;
        const uint32_t so = arr * AST + row * 144 + kc * 16;
        CP16(sb + so, (arr ? pB : pA) + go);
    }
    asm volatile("cp.async.commit_group;" ::: "memory");
}

__global__ __launch_bounds__(256) void gemm_f16(
    const __half* __restrict__ A, const __half* __restrict__ B,
    float* __restrict__ C, int ldc)
{
    extern __shared__ char sm[];
    const int t = threadIdx.x, wid = t >> 5, lane = t & 31;
    const int m0 = blockIdx.y * 128, nb = blockIdx.x * 128;
    const uint32_t smb = smem_u32(sm);

    const char* pA = (const char*)A + (size_t)m0 * 2048;
    const char* pB = (const char*)B + (size_t)nb * 2048;

    const int warp_m = (wid & 1) * 64;
    const int warp_n = (wid >> 1) * 32;
    const int a_m  = lane & 15;
    const int a_kb = lane >> 4;
    const int b_n  = (lane & 7) + ((lane >> 4) & 1) * 8;
    const int b_kb = (lane >> 3) & 1;

    float acc[4][4][4];
    #pragma unroll
    for (int im = 0; im < 4; im++)
        #pragma unroll
        for (int jn = 0; jn < 4; jn++)
            #pragma unroll
            for (int c = 0; c < 4; c++) acc[im][jn][c] = 0.0f;

    g_load_stage(smb,             pA, pB, t, 0);
    g_load_stage(smb + STG_B,     pA, pB, t, 1);
    g_load_stage(smb + 2 * STG_B, pA, pB, t, 2);

    int buf = 0;
    #pragma unroll 1
    for (int s = 0; s < 16; s++) {
        if (s < 14)       asm volatile("cp.async.wait_group 2;" ::: "memory");
        else if (s == 14) asm volatile("cp.async.wait_group 1;" ::: "memory");
        else              asm volatile("cp.async.wait_group 0;" ::: "memory");
        __syncthreads();

        const uint32_t sb = smb + buf * STG_B;
        #pragma unroll
        for (int kk = 0; kk < 4; kk++) {
            const uint32_t k0 = kk * 16;
            uint32_t a[4][4], b[2][4];
            const uint32_t aoff = (warp_m + a_m) * 144 + (k0 + a_kb * 8) * 2;
            #pragma unroll
            for (int im = 0; im < 4; im++)
                LDSM4(a[im], sb + aoff + im * (16 * 144));
            #pragma unroll
            for (int j2 = 0; j2 < 2; j2++) {
                const uint32_t boff = (warp_n + j2 * 16 + b_n) * 144 + (k0 + b_kb * 8) * 2;
                LDSM4(b[j2], sb + AST + boff);
            }
            #pragma unroll
            for (int im = 0; im < 4; im++)
                #pragma unroll
                for (int jn = 0; jn < 4; jn++) {
                    const int j2 = jn >> 1, jr = (jn & 1) * 2;
                    MMAF16(acc[im][jn], a[im], b[j2][jr], b[j2][jr + 1]);
                }
        }
        __syncthreads();
        if (s + 3 < 16) g_load_stage(sb, pA, pB, t, s + 3);
        buf = (buf == 2) ? 0 : buf + 1;
    }

    const int r0 = lane >> 2, c0 = (lane & 3) * 2;
    #pragma unroll
    for (int im = 0; im < 4; im++)
        #pragma unroll
        for (int jn = 0; jn < 4; jn++) {
            const int row = m0 + warp_m + im * 16 + r0;
            const int col = nb + warp_n + jn * 8 + c0;
            *(float2*)&C[(size_t)row * ldc + col] =
                make_float2(acc[im][jn][0], acc[im][jn][1]);
            *(float2*)&C[(size_t)(row + 8) * ldc + col] =
                make_float2(acc[im][jn][2], acc[im][jn][3]);
        }
}

// -------- postprocess: q/k norm+rotary (by<5) and v-gate (by>=5) --------
#define LOG2E 1.4426950408889634f
__global__ __launch_bounds__(128) void pp(const float* __restrict__ q_gain)
{
    const int m = blockIdx.x;
    const float* row = g_qkvg + (size_t)m * NTOT;

    if (blockIdx.y >= 5) {                        // v-gate: 2 blocks x 128 elems
        const int i = (blockIdx.y - 5) * 128 + threadIdx.x;   // < 256
        float v = row[1280 + i], g = row[1536 + i];
        float vg = v / (1.0f + __expf(-g));
        int kvh = i >> 6, d = i & 63, hf = d >> 5, dc = d & 31;
        size_t o = ((size_t)(kvh * 2 + hf) * S_LEN + m) * 32 + dc;
        g_av[o] = __float2half_rn(vg);
        return;
    }

    const int w = threadIdx.x >> 5, l = threadIdx.x & 31;
    const int unit = blockIdx.y * 4 + w;          // 0..19
    const bool isq = unit < 16;
    const int h = isq ? unit : unit - 16;
    const int col0 = isq ? h * HD : 1024 + h * HD;
    float x1 = row[col0 + l], x2 = row[col0 + l + 32];
    float ss = x1 * x1 + x2 * x2;
    #pragma unroll
    for (int o = 16; o > 0; o >>= 1) ss += __shfl_xor_sync(0xffffffffu, ss, o);
    const float rn = rsqrtf(ss * (1.0f / 64.0f) + 1.1920929e-7f);
    x1 *= rn; x2 *= rn;
    const float2 rc = g_rot[m * 32 + l];
    float y0 = x1 * rc.x + x2 * rc.y;
    float y1 = -x1 * rc.y + x2 * rc.x;
    const size_t o0 = ((size_t)(h * 2 + 0) * S_LEN + m) * 32 + l;
    const size_t o1 = ((size_t)(h * 2 + 1) * S_LEN + m) * 32 + l;
    if (isq) {
        const float gs = q_gain[h] * (0.17677669529663688f * LOG2E);
        g_aq[o0] = __float2half_rn(y0 * gs);
        g_aq[o1] = __float2half_rn(y1 * gs);
    } else {
        g_ak[o0] = __float2half_rn(y0);
        g_ak[o1] = __float2half_rn(y1);
    }
}

// -------- HMMA flash attention: per-head, both halves, fused combine -------
// grid (16 q-tiles, 16 heads), block 256 (8 warps x m16 rows).
// per stage: [k0, v0, k1, v1] tiles (64 rows x 80B each).
#define ATILE 5120
#define QTILE 10240
#define KVST  (4 * ATILE)              // 20480
#define ASMEM (2 * KVST + 2 * QTILE)   // 61440

__device__ __forceinline__ void a_load_kv(
    uint32_t sb, const char* k0, const char* v0,
    const char* k1, const char* v1, int t, int key0)
{
    #pragma unroll
    for (int j = 0; j < 4; j++) {
        const int c = t + 256 * j;                // 0..1023
        const int arr = c >> 8, rem = c & 255;    // arr: 0=k0 1=v0 2=k1 3=v1
        const int row = rem >> 2, c4 = rem & 3;
        const char* src = (arr == 0) ? k0 : (arr == 1) ? v0 : (arr == 2) ? k1 : v1;
        CP16(sb + arr * ATILE + row * 80 + c4 * 16,
             src + ((size_t)(key0 + row) * 32 + c4 * 8) * 2);
    }
    asm volatile("cp.async.commit_group;" ::: "memory");
}

__global__ __launch_bounds__(256) void attn_mma(const float* __restrict__ lambda_p)
{
    extern __shared__ char sm[];
    const int qt = gridDim.x - 1 - blockIdx.x;     // big q-tiles first
    const int h = blockIdx.y, kvh = h >> 2;
    const int t = threadIdx.x, w = t >> 5, l = t & 31;
    const int q0 = qt * 128;
    const uint32_t smb = smem_u32(sm);
    const uint32_t sQ = smb + 2 * KVST;            // [half0 | half1]

    const char* q_g0 = (const char*)(g_aq + ((size_t)(h * 2 + 0) * S_LEN + q0) * 32);
    const char* q_g1 = (const char*)(g_aq + ((size_t)(h * 2 + 1) * S_LEN + q0) * 32);
    const char* k_g0 = (const char*)(g_ak + (size_t)(kvh * 2 + 0) * S_LEN * 32);
    const char* k_g1 = (const char*)(g_ak + (size_t)(kvh * 2 + 1) * S_LEN * 32);
    const char* v_g0 = (const char*)(g_av + (size_t)(kvh * 2 + 0) * S_LEN * 32);
    const char* v_g1 = (const char*)(g_av + (size_t)(kvh * 2 + 1) * S_LEN * 32);

    // Q both halves: 1024 CP16s
    #pragma unroll
    for (int j = 0; j < 4; j++) {
        const int c = t + 256 * j;
        const int half = c >> 9, rem = c & 511;
        const int row = rem >> 2, c4 = rem & 3;
        CP16(sQ + half * QTILE + row * 80 + c4 * 16,
             (half ? q_g1 : q_g0) + ((size_t)row * 32 + c4 * 8) * 2);
    }
    a_load_kv(smb, k_g0, v_g0, k_g1, v_g1, t, 0);
    const int nt = 2 * qt + 2;
    if (nt > 1) a_load_kv(smb + KVST, k_g0, v_g0, k_g1, v_g1, t, 64);

    uint32_t qf[2][2][4];
    float O[2][4][4];
    #pragma unroll
    for (int hf = 0; hf < 2; hf++)
        #pragma unroll
        for (int nd = 0; nd < 4; nd++)
            #pragma unroll
            for (int c = 0; c < 4; c++) O[hf][nd][c] = 0.0f;
    float lp[2][2] = {{0.0f, 0.0f}, {0.0f, 0.0f}};

    const int row0 = q0 + w * 16 + (l >> 2);
    const int qmax_w = q0 + w * 16 + 15;
    const int qmin_w = q0 + w * 16;

    #pragma unroll 1
    for (int i = 0; i < nt; i++) {
        if (i + 1 < nt) asm volatile("cp.async.wait_group 1;" ::: "memory");
        else            asm volatile("cp.async.wait_group 0;" ::: "memory");
        __syncthreads();

        if (i == 0) {
            const uint32_t qoff = (w * 16 + (l & 15)) * 80 + ((l >> 4) * 8) * 2;
            #pragma unroll
            for (int hf = 0; hf < 2; hf++) {
                LDSM4(qf[hf][0], sQ + hf * QTILE + qoff);
                LDSM4(qf[hf][1], sQ + hf * QTILE + qoff + 32);
            }
        }

        const uint32_t sb = smb + (i & 1) * KVST;
        const int key0 = i * 64;

        if (key0 <= qmax_w) {
            const bool diag = (key0 + 63 > qmin_w);
            #pragma unroll
            for (int hf = 0; hf < 2; hf++) {
                const uint32_t skv = sb + hf * 2 * ATILE;
                float s[8][4];
                #pragma unroll
                for (int n = 0; n < 8; n++)
                    #pragma unroll
                    for (int c = 0; c < 4; c++) s[n][c] = 0.0f;

                #pragma unroll
                for (int ks = 0; ks < 2; ks++) {
                    #pragma unroll
                    for (int g = 0; g < 4; g++) {
                        uint32_t kf[4];
                        const uint32_t ka = skv
                            + (g * 16 + (l & 7) + ((l >> 4) & 1) * 8) * 80
                            + (ks * 16 + ((l >> 3) & 1) * 8) * 2;
                        LDSM4(kf, ka);
                        MMAF16(s[2*g],   qf[hf][ks], kf[0], kf[1]);
                        MMAF16(s[2*g+1], qf[hf][ks], kf[2], kf[3]);
                    }
                }

                if (diag) {
                    #pragma unroll
                    for (int n = 0; n < 8; n++) {
                        const int cb = key0 + n * 8 + (l & 3) * 2;
                        if (cb     > row0)     s[n][0] = -1e30f;
                        if (cb + 1 > row0)     s[n][1] = -1e30f;
                        if (cb     > row0 + 8) s[n][2] = -1e30f;
                        if (cb + 1 > row0 + 8) s[n][3] = -1e30f;
                    }
                }

                uint32_t aP[4][4];
                #pragma unroll
                for (int j = 0; j < 4; j++) {
                    #pragma unroll
                    for (int q = 0; q < 2; q++) {
                        const int n = 2 * j + q;
                        float p0, p1, p2, p3;
                        EX2(p0, s[n][0]);
                        EX2(p1, s[n][1]);
                        EX2(p2, s[n][2]);
                        EX2(p3, s[n][3]);
                        lp[hf][0] += p0 + p1;
                        lp[hf][1] += p2 + p3;
                        PACKF16(aP[j][2*q],     p0, p1);
                        PACKF16(aP[j][2*q + 1], p2, p3);
                    }
                }

                #pragma unroll
                for (int j = 0; j < 4; j++) {
                    #pragma unroll
                    for (int dg = 0; dg < 2; dg++) {
                        uint32_t vf[4];
                        const uint32_t va = skv + ATILE
                            + (16 * j + (l & 7) + ((l >> 3) & 1) * 8) * 80
                            + (dg * 16 + ((l >> 4) & 1) * 8) * 2;
                        LDSM4T(vf, va);
                        MMAF16(O[hf][2*dg],     aP[j], vf[0], vf[1]);
                        MMAF16(O[hf][2*dg + 1], aP[j], vf[2], vf[3]);
                    }
                }
            }
        }

        __syncthreads();
        if (i + 2 < nt)
            a_load_kv(sb, k_g0, v_g0, k_g1, v_g1, t, (i + 2) * 64);
    }

    // reduce softmax denominators across the 4 lanes of each accum row
    #pragma unroll
    for (int hf = 0; hf < 2; hf++)
        #pragma unroll
        for (int r = 0; r < 2; r++) {
            lp[hf][r] += __shfl_xor_sync(0xffffffffu, lp[hf][r], 1);
            lp[hf][r] += __shfl_xor_sync(0xffffffffu, lp[hf][r], 2);
        }
    const float inv00 = 1.0f / lp[0][0], inv01 = 1.0f / lp[0][1];
    const float inv10 = 1.0f / lp[1][0], inv11 = 1.0f / lp[1][1];
    const float lam = lambda_p[h];

    // fused differential combine -> fp16 y
    #pragma unroll
    for (int nd = 0; nd < 4; nd++) {
        const int col = nd * 8 + (l & 3) * 2;     // 0..31 within half
        #pragma unroll
        for (int r = 0; r < 2; r++) {             // row0, row0+8
            const int m = row0 + r * 8;
            const float i0 = r ? inv01 : inv00;
            const float i1 = r ? inv11 : inv10;
            const float a1a = O[0][nd][2*r]     * i0;
            const float a1b = O[0][nd][2*r + 1] * i0;
            const float a2a = O[1][nd][2*r]     * i1;
            const float a2b = O[1][nd][2*r + 1] * i1;
            __half* yp = g_yh + (size_t)m * DIM + h * HD + col;
            *(__half2*)yp        = __floats2half2_rn(a1a - lam * a2a, a1b - lam * a2b);
            *(__half2*)(yp + 32) = __floats2half2_rn(a1a + lam * a2a, a1b + lam * a2b);
        }
    }
}

extern "C" void kernel_launch(void* const* d_in, const int* in_sizes, int n_in,
                              void* d_out, int out_size)
{
    const float* x        = (const float*)d_in[0];
    const float* Wq       = (const float*)d_in[1];
    const float* Wk       = (const float*)d_in[2];
    const float* Wv       = (const float*)d_in[3];
    const float* Wg       = (const float*)d_in[4];
    const float* Wo       = (const float*)d_in[5];
    const float* q_gain   = (const float*)d_in[6];
    const float* lambda_p = (const float*)d_in[7];
    float* out = (float*)d_out;

    cudaFuncSetAttribute(gemm_f16, cudaFuncAttributeMaxDynamicSharedMemorySize, GSMEM);
    cudaFuncSetAttribute(attn_mma, cudaFuncAttributeMaxDynamicSharedMemorySize, ASMEM);

    float* qkvg_p;
    __half *xh, *wh, *woh, *yh;
    cudaGetSymbolAddress((void**)&qkvg_p, g_qkvg);
    cudaGetSymbolAddress((void**)&xh, g_xh);
    cudaGetSymbolAddress((void**)&wh, g_wh);
    cudaGetSymbolAddress((void**)&woh, g_woh);
    cudaGetSymbolAddress((void**)&yh, g_yh);

    conv_all<<<5120, 256>>>(x, Wq, Wk, Wv, Wg, Wo);
    gemm_f16<<<dim3(NTOT/128, S_LEN/128), 256, GSMEM>>>(xh, wh, qkvg_p, NTOT);
    pp<<<dim3(S_LEN, 7), 128>>>(q_gain);
    attn_mma<<<dim3(S_LEN/128, NH), 256, ASMEM>>>(lambda_p);
    gemm_f16<<<dim3(DIM/128, S_LEN/128), 256, GSMEM>>>(yh, woh, out, DIM);
}

// round 12
// speedup vs baseline: 1.1028x; 1.1028x over previous
#include <cuda_runtime.h>
#include <cuda_bf16.h>
#include <cuda_fp16.h>
#include <math.h>
#include <stdint.h>

#define S_LEN 2048
#define DIM 1024
#define NH 16
#define KVH 4
#define HD 64
#define NTOT 1792

__device__ float g_qkvg[S_LEN * NTOT];
__device__ float2 g_rot[S_LEN * 32];
__device__ __half g_xh[S_LEN * DIM];
__device__ __half g_wh[NTOT * DIM];
__device__ __half g_woh[DIM * DIM];
__device__ __half g_yh[S_LEN * DIM];
// attention operands, single fp16, layout [(head*2+half)][seq][32]
__device__ __half g_aq[NH*2*S_LEN*32];
__device__ __half g_ak[KVH*2*S_LEN*32];
__device__ __half g_av[KVH*2*S_LEN*32];

__device__ __forceinline__ uint32_t smem_u32(const void* p) {
    uint32_t a;
    asm("{ .reg .u64 t; cvta.to.shared.u64 t, %1; cvt.u32.u64 %0, t; }" : "=r"(a) : "l"(p));
    return a;
}
#define CP16(sm, gp) asm volatile("cp.async.cg.shared.global [%0], [%1], 16;" :: "r"(sm), "l"(gp))
#define LDSM4(r, addr) \
    asm volatile("ldmatrix.sync.aligned.m8n8.x4.shared.b16 {%0,%1,%2,%3}, [%4];" \
        : "=r"((r)[0]), "=r"((r)[1]), "=r"((r)[2]), "=r"((r)[3]) : "r"(addr))
#define LDSM4T(r, addr) \
    asm volatile("ldmatrix.sync.aligned.m8n8.x4.trans.shared.b16 {%0,%1,%2,%3}, [%4];" \
        : "=r"((r)[0]), "=r"((r)[1]), "=r"((r)[2]), "=r"((r)[3]) : "r"(addr))
#define MMAF16(d, a, b0, b1) \
    asm volatile("mma.sync.aligned.m16n8k16.row.col.f32.f16.f16.f32 " \
        "{%0,%1,%2,%3}, {%4,%5,%6,%7}, {%8,%9}, {%0,%1,%2,%3};" \
        : "+f"((d)[0]), "+f"((d)[1]), "+f"((d)[2]), "+f"((d)[3]) \
        : "r"((a)[0]), "r"((a)[1]), "r"((a)[2]), "r"((a)[3]), "r"(b0), "r"(b1))
#define PACKF16(r, a, b) asm("cvt.rn.f16x2.f32 %0, %1, %2;" : "=r"(r) : "f"(b), "f"(a))
#define EX2(d, x) asm("ex2.approx.ftz.f32 %0, %1;" : "=f"(d) : "f"(x))

// -------- fused fp32 -> fp16 conversion for all 6 tensors + rotary table ----
__global__ __launch_bounds__(256) void conv_all(
    const float* __restrict__ x,  const float* __restrict__ Wq,
    const float* __restrict__ Wk, const float* __restrict__ Wv,
    const float* __restrict__ Wg, const float* __restrict__ Wo)
{
    if (blockIdx.x >= 4864) {                       // rotary-table tail blocks
        const int i = (blockIdx.x - 4864) * 256 + threadIdx.x;   // < 65536
        const int m = i >> 5, t = i & 31;
        const float angle = ((float)(2 * t) / 64.0f) * 3.14159274101257324f;
        const float ang = (float)m * angle;
        double a = (double)ang;
        a -= rint(a * 0.15915494309189535) * 6.283185307179586;
        float c, sn;
        sincosf((float)a, &sn, &c);
        const float radius = 1.0f / (1.0f + (float)m * 0.01f);
        g_rot[i] = make_float2(c * radius, sn * radius);
        return;
    }
    const int i = blockIdx.x * 256 + threadIdx.x;
    const float* s; __half* d;
    if (i < 524288)      { size_t j = (size_t)i * 4;            s = x  + j; d = g_xh + j; }
    else if (i < 786432) { size_t j = (size_t)(i - 524288) * 4; s = Wq + j; d = g_wh + j; }
    else if (i < 851968) { size_t j = (size_t)(i - 786432) * 4; s = Wk + j; d = g_wh + 1048576 + j; }
    else if (i < 917504) { size_t j = (size_t)(i - 851968) * 4; s = Wv + j; d = g_wh + 1310720 + j; }
    else if (i < 983040) { size_t j = (size_t)(i - 917504) * 4; s = Wg + j; d = g_wh + 1572864 + j; }
    else                 { size_t j = (size_t)(i - 983040) * 4; s = Wo + j; d = g_woh + j; }
    float4 v = *(const float4*)s;
    __half2 h0 = __floats2half2_rn(v.x, v.y);
    __half2 h1 = __floats2half2_rn(v.z, v.w);
    *(__half2*)d = h0; *(__half2*)(d + 2) = h1;
}

// -------- fp16 HMMA GEMM: C[M,N] = A[M,K] @ B[N,K]^T, 3-stage --------
#define AST   18432
#define STG_B (2 * AST)
#define GSMEM (3 * STG_B)           // 110592

__device__ __forceinline__ void g_load_stage(
    uint32_t sb, const char* pA, const char* pB, int t, int s)
{
    const size_t gk = (size_t)s * 128;
    #pragma unroll
    for (int j = 0; j < 8; j++) {
        const int idx = t + 256 * j;
        const int arr = idx >> 10, rem = idx & 1023;
        const int row = rem >> 3, kc = rem & 7;
        const size_t go = (size_t)row * 2048 + gk + kc * 16;
        const uint32_t so = arr * AST + row * 144 + kc * 16;
        CP16(sb + so, (arr ? pB : pA) + go);
    }
    asm volatile("cp.async.commit_group;" ::: "memory");
}

__global__ __launch_bounds__(256) void gemm_f16(
    const __half* __restrict__ A, const __half* __restrict__ B,
    float* __restrict__ C, int ldc)
{
    extern __shared__ char sm[];
    const int t = threadIdx.x, wid = t >> 5, lane = t & 31;
    const int m0 = blockIdx.y * 128, nb = blockIdx.x * 128;
    const uint32_t smb = smem_u32(sm);

    const char* pA = (const char*)A + (size_t)m0 * 2048;
    const char* pB = (const char*)B + (size_t)nb * 2048;

    const int warp_m = (wid & 1) * 64;
    const int warp_n = (wid >> 1) * 32;
    const int a_m  = lane & 15;
    const int a_kb = lane >> 4;
    const int b_n  = (lane & 7) + ((lane >> 4) & 1) * 8;
    const int b_kb = (lane >> 3) & 1;

    float acc[4][4][4];
    #pragma unroll
    for (int im = 0; im < 4; im++)
        #pragma unroll
        for (int jn = 0; jn < 4; jn++)
            #pragma unroll
            for (int c = 0; c < 4; c++) acc[im][jn][c] = 0.0f;

    g_load_stage(smb,             pA, pB, t, 0);
    g_load_stage(smb + STG_B,     pA, pB, t, 1);
    g_load_stage(smb + 2 * STG_B, pA, pB, t, 2);

    int buf = 0;
    #pragma unroll 1
    for (int s = 0; s < 16; s++) {
        if (s < 14)       asm volatile("cp.async.wait_group 2;" ::: "memory");
        else if (s == 14) asm volatile("cp.async.wait_group 1;" ::: "memory");
        else              asm volatile("cp.async.wait_group 0;" ::: "memory");
        __syncthreads();

        const uint32_t sb = smb + buf * STG_B;
        #pragma unroll
        for (int kk = 0; kk < 4; kk++) {
            const uint32_t k0 = kk * 16;
            uint32_t a[4][4], b[2][4];
            const uint32_t aoff = (warp_m + a_m) * 144 + (k0 + a_kb * 8) * 2;
            #pragma unroll
            for (int im = 0; im < 4; im++)
                LDSM4(a[im], sb + aoff + im * (16 * 144));
            #pragma unroll
            for (int j2 = 0; j2 < 2; j2++) {
                const uint32_t boff = (warp_n + j2 * 16 + b_n) * 144 + (k0 + b_kb * 8) * 2;
                LDSM4(b[j2], sb + AST + boff);
            }
            #pragma unroll
            for (int im = 0; im < 4; im++)
                #pragma unroll
                for (int jn = 0; jn < 4; jn++) {
                    const int j2 = jn >> 1, jr = (jn & 1) * 2;
                    MMAF16(acc[im][jn], a[im], b[j2][jr], b[j2][jr + 1]);
                }
        }
        __syncthreads();
        if (s + 3 < 16) g_load_stage(sb, pA, pB, t, s + 3);
        buf = (buf == 2) ? 0 : buf + 1;
    }

    const int r0 = lane >> 2, c0 = (lane & 3) * 2;
    #pragma unroll
    for (int im = 0; im < 4; im++)
        #pragma unroll
        for (int jn = 0; jn < 4; jn++) {
            const int row = m0 + warp_m + im * 16 + r0;
            const int col = nb + warp_n + jn * 8 + c0;
            *(float2*)&C[(size_t)row * ldc + col] =
                make_float2(acc[im][jn][0], acc[im][jn][1]);
            *(float2*)&C[(size_t)(row + 8) * ldc + col] =
                make_float2(acc[im][jn][2], acc[im][jn][3]);
        }
}

// -------- postprocess: q/k norm+rotary (by<5) and v-gate (by>=5) --------
#define LOG2E 1.4426950408889634f
__global__ __launch_bounds__(128) void pp(const float* __restrict__ q_gain)
{
    const int m = blockIdx.x;
    const float* row = g_qkvg + (size_t)m * NTOT;

    if (blockIdx.y >= 5) {                        // v-gate: 2 blocks x 128 elems
        const int i = (blockIdx.y - 5) * 128 + threadIdx.x;   // < 256
        float v = row[1280 + i], g = row[1536 + i];
        float vg = v / (1.0f + __expf(-g));
        int kvh = i >> 6, d = i & 63, hf = d >> 5, dc = d & 31;
        size_t o = ((size_t)(kvh * 2 + hf) * S_LEN + m) * 32 + dc;
        g_av[o] = __float2half_rn(vg);
        return;
    }

    const int w = threadIdx.x >> 5, l = threadIdx.x & 31;
    const int unit = blockIdx.y * 4 + w;          // 0..19
    const bool isq = unit < 16;
    const int h = isq ? unit : unit - 16;
    const int col0 = isq ? h * HD : 1024 + h * HD;
    float x1 = row[col0 + l], x2 = row[col0 + l + 32];
    float ss = x1 * x1 + x2 * x2;
    #pragma unroll
    for (int o = 16; o > 0; o >>= 1) ss += __shfl_xor_sync(0xffffffffu, ss, o);
    const float rn = rsqrtf(ss * (1.0f / 64.0f) + 1.1920929e-7f);
    x1 *= rn; x2 *= rn;
    const float2 rc = g_rot[m * 32 + l];
    float y0 = x1 * rc.x + x2 * rc.y;
    float y1 = -x1 * rc.y + x2 * rc.x;
    const size_t o0 = ((size_t)(h * 2 + 0) * S_LEN + m) * 32 + l;
    const size_t o1 = ((size_t)(h * 2 + 1) * S_LEN + m) * 32 + l;
    if (isq) {
        const float gs = q_gain[h] * (0.17677669529663688f * LOG2E);
        g_aq[o0] = __float2half_rn(y0 * gs);
        g_aq[o1] = __float2half_rn(y1 * gs);
    } else {
        g_ak[o0] = __float2half_rn(y0);
        g_ak[o1] = __float2half_rn(y1);
    }
}

// -------- HMMA flash attention: 64 q-rows, 4 warps, both halves, fused combine
// grid (32 q-tiles, 16 heads), block 128. 3 CTAs/SM (regs<=170, smem 51200).
#define ATILE 5120                     // 64 rows * 80B
#define QTILE 5120                     // 64 rows * 80B
#define KVST  (4 * ATILE)              // k0,v0,k1,v1 = 20480
#define ASMEM (2 * KVST + 2 * QTILE)   // 51200

__device__ __forceinline__ void a_load_kv(
    uint32_t sb, const char* k0, const char* v0,
    const char* k1, const char* v1, int t, int key0)
{
    #pragma unroll
    for (int j = 0; j < 8; j++) {
        const int c = t + 128 * j;                // 0..1023
        const int arr = c >> 8, rem = c & 255;    // arr: 0=k0 1=v0 2=k1 3=v1
        const int row = rem >> 2, c4 = rem & 3;
        const char* src = (arr == 0) ? k0 : (arr == 1) ? v0 : (arr == 2) ? k1 : v1;
        CP16(sb + arr * ATILE + row * 80 + c4 * 16,
             src + ((size_t)(key0 + row) * 32 + c4 * 8) * 2);
    }
    asm volatile("cp.async.commit_group;" ::: "memory");
}

__global__ __launch_bounds__(128, 3) void attn_mma(const float* __restrict__ lambda_p)
{
    extern __shared__ char sm[];
    const int qt = gridDim.x - 1 - blockIdx.x;     // big q-tiles first
    const int h = blockIdx.y, kvh = h >> 2;
    const int t = threadIdx.x, w = t >> 5, l = t & 31;
    const int q0 = qt * 64;
    const uint32_t smb = smem_u32(sm);
    const uint32_t sQ = smb + 2 * KVST;            // [half0 | half1]

    const char* q_g0 = (const char*)(g_aq + ((size_t)(h * 2 + 0) * S_LEN + q0) * 32);
    const char* q_g1 = (const char*)(g_aq + ((size_t)(h * 2 + 1) * S_LEN + q0) * 32);
    const char* k_g0 = (const char*)(g_ak + (size_t)(kvh * 2 + 0) * S_LEN * 32);
    const char* k_g1 = (const char*)(g_ak + (size_t)(kvh * 2 + 1) * S_LEN * 32);
    const char* v_g0 = (const char*)(g_av + (size_t)(kvh * 2 + 0) * S_LEN * 32);
    const char* v_g1 = (const char*)(g_av + (size_t)(kvh * 2 + 1) * S_LEN * 32);

    // Q both halves: 512 CP16s
    #pragma unroll
    for (int j = 0; j < 4; j++) {
        const int c = t + 128 * j;                // 0..511
        const int half = c >> 8, rem = c & 255;
        const int row = rem >> 2, c4 = rem & 3;
        CP16(sQ + half * QTILE + row * 80 + c4 * 16,
             (half ? q_g1 : q_g0) + ((size_t)row * 32 + c4 * 8) * 2);
    }
    a_load_kv(smb, k_g0, v_g0, k_g1, v_g1, t, 0);
    const int nt = qt + 1;                         // keys 0 .. q0+63
    if (nt > 1) a_load_kv(smb + KVST, k_g0, v_g0, k_g1, v_g1, t, 64);

    uint32_t qf[2][2][4];
    float O[2][4][4];
    #pragma unroll
    for (int hf = 0; hf < 2; hf++)
        #pragma unroll
        for (int nd = 0; nd < 4; nd++)
            #pragma unroll
            for (int c = 0; c < 4; c++) O[hf][nd][c] = 0.0f;
    float lp[2][2] = {{0.0f, 0.0f}, {0.0f, 0.0f}};

    const int row0 = q0 + w * 16 + (l >> 2);
    const int qmax_w = q0 + w * 16 + 15;
    const int qmin_w = q0 + w * 16;

    #pragma unroll 1
    for (int i = 0; i < nt; i++) {
        if (i + 1 < nt) asm volatile("cp.async.wait_group 1;" ::: "memory");
        else            asm volatile("cp.async.wait_group 0;" ::: "memory");
        __syncthreads();

        if (i == 0) {
            const uint32_t qoff = (w * 16 + (l & 15)) * 80 + ((l >> 4) * 8) * 2;
            #pragma unroll
            for (int hf = 0; hf < 2; hf++) {
                LDSM4(qf[hf][0], sQ + hf * QTILE + qoff);
                LDSM4(qf[hf][1], sQ + hf * QTILE + qoff + 32);
            }
        }

        const uint32_t sb = smb + (i & 1) * KVST;
        const int key0 = i * 64;

        if (key0 <= qmax_w) {
            const bool diag = (key0 + 63 > qmin_w);
            #pragma unroll
            for (int hf = 0; hf < 2; hf++) {
                const uint32_t skv = sb + hf * 2 * ATILE;
                float s[8][4];
                #pragma unroll
                for (int n = 0; n < 8; n++)
                    #pragma unroll
                    for (int c = 0; c < 4; c++) s[n][c] = 0.0f;

                #pragma unroll
                for (int ks = 0; ks < 2; ks++) {
                    #pragma unroll
                    for (int g = 0; g < 4; g++) {
                        uint32_t kf[4];
                        const uint32_t ka = skv
                            + (g * 16 + (l & 7) + ((l >> 4) & 1) * 8) * 80
                            + (ks * 16 + ((l >> 3) & 1) * 8) * 2;
                        LDSM4(kf, ka);
                        MMAF16(s[2*g],   qf[hf][ks], kf[0], kf[1]);
                        MMAF16(s[2*g+1], qf[hf][ks], kf[2], kf[3]);
                    }
                }

                if (diag) {
                    #pragma unroll
                    for (int n = 0; n < 8; n++) {
                        const int cb = key0 + n * 8 + (l & 3) * 2;
                        if (cb     > row0)     s[n][0] = -1e30f;
                        if (cb + 1 > row0)     s[n][1] = -1e30f;
                        if (cb     > row0 + 8) s[n][2] = -1e30f;
                        if (cb + 1 > row0 + 8) s[n][3] = -1e30f;
                    }
                }

                uint32_t aP[4][4];
                #pragma unroll
                for (int j = 0; j < 4; j++) {
                    #pragma unroll
                    for (int q = 0; q < 2; q++) {
                        const int n = 2 * j + q;
                        float p0, p1, p2, p3;
                        EX2(p0, s[n][0]);
                        EX2(p1, s[n][1]);
                        EX2(p2, s[n][2]);
                        EX2(p3, s[n][3]);
                        lp[hf][0] += p0 + p1;
                        lp[hf][1] += p2 + p3;
                        PACKF16(aP[j][2*q],     p0, p1);
                        PACKF16(aP[j][2*q + 1], p2, p3);
                    }
                }

                #pragma unroll
                for (int j = 0; j < 4; j++) {
                    #pragma unroll
                    for (int dg = 0; dg < 2; dg++) {
                        uint32_t vf[4];
                        const uint32_t va = skv + ATILE
                            + (16 * j + (l & 7) + ((l >> 3) & 1) * 8) * 80
                            + (dg * 16 + ((l >> 4) & 1) * 8) * 2;
                        LDSM4T(vf, va);
                        MMAF16(O[hf][2*dg],     aP[j], vf[0], vf[1]);
                        MMAF16(O[hf][2*dg + 1], aP[j], vf[2], vf[3]);
                    }
                }
            }
        }

        __syncthreads();
        if (i + 2 < nt)
            a_load_kv(sb, k_g0, v_g0, k_g1, v_g1, t, (i + 2) * 64);
    }

    #pragma unroll
    for (int hf = 0; hf < 2; hf++)
        #pragma unroll
        for (int r = 0; r < 2; r++) {
            lp[hf][r] += __shfl_xor_sync(0xffffffffu, lp[hf][r], 1);
            lp[hf][r] += __shfl_xor_sync(0xffffffffu, lp[hf][r], 2);
        }
    const float inv00 = 1.0f / lp[0][0], inv01 = 1.0f / lp[0][1];
    const float inv10 = 1.0f / lp[1][0], inv11 = 1.0f / lp[1][1];
    const float lam = lambda_p[h];

    // fused differential combine -> fp16 y
    #pragma unroll
    for (int nd = 0; nd < 4; nd++) {
        const int col = nd * 8 + (l & 3) * 2;
        #pragma unroll
        for (int r = 0; r < 2; r++) {
            const int m = row0 + r * 8;
            const float i0 = r ? inv01 : inv00;
            const float i1 = r ? inv11 : inv10;
            const float a1a = O[0][nd][2*r]     * i0;
            const float a1b = O[0][nd][2*r + 1] * i0;
            const float a2a = O[1][nd][2*r]     * i1;
            const float a2b = O[1][nd][2*r + 1] * i1;
            __half* yp = g_yh + (size_t)m * DIM + h * HD + col;
            *(__half2*)yp        = __floats2half2_rn(a1a - lam * a2a, a1b - lam * a2b);
            *(__half2*)(yp + 32) = __floats2half2_rn(a1a + lam * a2a, a1b + lam * a2b);
        }
    }
}

extern "C" void kernel_launch(void* const* d_in, const int* in_sizes, int n_in,
                              void* d_out, int out_size)
{
    const float* x        = (const float*)d_in[0];
    const float* Wq       = (const float*)d_in[1];
    const float* Wk       = (const float*)d_in[2];
    const float* Wv       = (const float*)d_in[3];
    const float* Wg       = (const float*)d_in[4];
    const float* Wo       = (const float*)d_in[5];
    const float* q_gain   = (const float*)d_in[6];
    const float* lambda_p = (const float*)d_in[7];
    float* out = (float*)d_out;

    cudaFuncSetAttribute(gemm_f16, cudaFuncAttributeMaxDynamicSharedMemorySize, GSMEM);
    cudaFuncSetAttribute(attn_mma, cudaFuncAttributeMaxDynamicSharedMemorySize, ASMEM);

    float* qkvg_p;
    __half *xh, *wh, *woh, *yh;
    cudaGetSymbolAddress((void**)&qkvg_p, g_qkvg);
    cudaGetSymbolAddress((void**)&xh, g_xh);
    cudaGetSymbolAddress((void**)&wh, g_wh);
    cudaGetSymbolAddress((void**)&woh, g_woh);
    cudaGetSymbolAddress((void**)&yh, g_yh);

    conv_all<<<5120, 256>>>(x, Wq, Wk, Wv, Wg, Wo);
    gemm_f16<<<dim3(NTOT/128, S_LEN/128), 256, GSMEM>>>(xh, wh, qkvg_p, NTOT);
    pp<<<dim3(S_LEN, 7), 128>>>(q_gain);
    attn_mma<<<dim3(S_LEN/64, NH), 128, ASMEM>>>(lambda_p);
    gemm_f16<<<dim3(DIM/128, S_LEN/128), 256, GSMEM>>>(yh, woh, out, DIM);
}

// round 13
// speedup vs baseline: 1.1031x; 1.0003x over previous
#include <cuda_runtime.h>
#include <cuda_bf16.h>
#include <cuda_fp16.h>
#include <math.h>
#include <stdint.h>

#define S_LEN 2048
#define DIM 1024
#define NH 16
#define KVH 4
#define HD 64
#define NTOT 1792

__device__ __half g_qkvg[S_LEN * NTOT];        // fp16 now
__device__ float2 g_rot[S_LEN * 32];
__device__ __half g_xh[S_LEN * DIM];
__device__ __half g_wh[NTOT * DIM];
__device__ __half g_woh[DIM * DIM];
__device__ __half g_yh[S_LEN * DIM];
__device__ __half g_aq[NH*2*S_LEN*32];
__device__ __half g_ak[KVH*2*S_LEN*32];
__device__ __half g_av[KVH*2*S_LEN*32];

__device__ __forceinline__ uint32_t smem_u32(const void* p) {
    uint32_t a;
    asm("{ .reg .u64 t; cvta.to.shared.u64 t, %1; cvt.u32.u64 %0, t; }" : "=r"(a) : "l"(p));
    return a;
}
#define CP16(sm, gp) asm volatile("cp.async.cg.shared.global [%0], [%1], 16;" :: "r"(sm), "l"(gp))
#define LDSM4(r, addr) \
    asm volatile("ldmatrix.sync.aligned.m8n8.x4.shared.b16 {%0,%1,%2,%3}, [%4];" \
        : "=r"((r)[0]), "=r"((r)[1]), "=r"((r)[2]), "=r"((r)[3]) : "r"(addr))
#define LDSM4T(r, addr) \
    asm volatile("ldmatrix.sync.aligned.m8n8.x4.trans.shared.b16 {%0,%1,%2,%3}, [%4];" \
        : "=r"((r)[0]), "=r"((r)[1]), "=r"((r)[2]), "=r"((r)[3]) : "r"(addr))
#define MMAF16(d, a, b0, b1) \
    asm volatile("mma.sync.aligned.m16n8k16.row.col.f32.f16.f16.f32 " \
        "{%0,%1,%2,%3}, {%4,%5,%6,%7}, {%8,%9}, {%0,%1,%2,%3};" \
        : "+f"((d)[0]), "+f"((d)[1]), "+f"((d)[2]), "+f"((d)[3]) \
        : "r"((a)[0]), "r"((a)[1]), "r"((a)[2]), "r"((a)[3]), "r"(b0), "r"(b1))
#define PACKF16(r, a, b) asm("cvt.rn.f16x2.f32 %0, %1, %2;" : "=r"(r) : "f"(b), "f"(a))
#define EX2(d, x) asm("ex2.approx.ftz.f32 %0, %1;" : "=f"(d) : "f"(x))

// -------- conversion: one float4 -> fp16x4 --------
__device__ __forceinline__ void conv_one(
    int i, const float* __restrict__ x,  const float* __restrict__ Wq,
    const float* __restrict__ Wk, const float* __restrict__ Wv,
    const float* __restrict__ Wg, const float* __restrict__ Wo)
{
    const float* s; __half* d;
    if (i < 524288)      { size_t j = (size_t)i * 4;            s = x  + j; d = g_xh + j; }
    else if (i < 786432) { size_t j = (size_t)(i - 524288) * 4; s = Wq + j; d = g_wh + j; }
    else if (i < 851968) { size_t j = (size_t)(i - 786432) * 4; s = Wk + j; d = g_wh + 1048576 + j; }
    else if (i < 917504) { size_t j = (size_t)(i - 851968) * 4; s = Wv + j; d = g_wh + 1310720 + j; }
    else if (i < 983040) { size_t j = (size_t)(i - 917504) * 4; s = Wg + j; d = g_wh + 1572864 + j; }
    else                 { size_t j = (size_t)(i - 983040) * 4; s = Wo + j; d = g_woh + j; }
    float4 v = *(const float4*)s;
    *(__half2*)d       = __floats2half2_rn(v.x, v.y);
    *(__half2*)(d + 2) = __floats2half2_rn(v.z, v.w);
}

// grid: 2432 conv blocks (x2 ILP) + 256 rotary blocks
__global__ __launch_bounds__(256) void conv_all(
    const float* __restrict__ x,  const float* __restrict__ Wq,
    const float* __restrict__ Wk, const float* __restrict__ Wv,
    const float* __restrict__ Wg, const float* __restrict__ Wo)
{
    if (blockIdx.x >= 2432) {                       // rotary-table tail
        const int i = (blockIdx.x - 2432) * 256 + threadIdx.x;   // < 65536
        const int m = i >> 5, t = i & 31;
        const float angle = ((float)(2 * t) / 64.0f) * 3.14159274101257324f;
        const float ang = (float)m * angle;
        double a = (double)ang;
        a -= rint(a * 0.15915494309189535) * 6.283185307179586;
        float c, sn;
        sincosf((float)a, &sn, &c);
        const float radius = 1.0f / (1.0f + (float)m * 0.01f);
        g_rot[i] = make_float2(c * radius, sn * radius);
        return;
    }
    const int i = blockIdx.x * 256 + threadIdx.x;   // < 622592
    conv_one(i,          x, Wq, Wk, Wv, Wg, Wo);
    conv_one(i + 622592, x, Wq, Wk, Wv, Wg, Wo);
}

// -------- fp16 HMMA GEMM: C[M,N] = A[M,K] @ B[N,K]^T, 3-stage --------
#define AST   18432
#define STG_B (2 * AST)
#define GSMEM (3 * STG_B)           // 110592

__device__ __forceinline__ void g_load_stage(
    uint32_t sb, const char* pA, const char* pB, int t, int s)
{
    const size_t gk = (size_t)s * 128;
    #pragma unroll
    for (int j = 0; j < 8; j++) {
        const int idx = t + 256 * j;
        const int arr = idx >> 10, rem = idx & 1023;
        const int row = rem >> 3, kc = rem & 7;
        const size_t go = (size_t)row * 2048 + gk + kc * 16;
        const uint32_t so = arr * AST + row * 144 + kc * 16;
        CP16(sb + so, (arr ? pB : pA) + go);
    }
    asm volatile("cp.async.commit_group;" ::: "memory");
}

template <typename TO>
__global__ __launch_bounds__(256) void gemm_f16(
    const __half* __restrict__ A, const __half* __restrict__ B,
    TO* __restrict__ C, int ldc)
{
    extern __shared__ char sm[];
    const int t = threadIdx.x, wid = t >> 5, lane = t & 31;
    const int m0 = blockIdx.y * 128, nb = blockIdx.x * 128;
    const uint32_t smb = smem_u32(sm);

    const char* pA = (const char*)A + (size_t)m0 * 2048;
    const char* pB = (const char*)B + (size_t)nb * 2048;

    const int warp_m = (wid & 1) * 64;
    const int warp_n = (wid >> 1) * 32;
    const int a_m  = lane & 15;
    const int a_kb = lane >> 4;
    const int b_n  = (lane & 7) + ((lane >> 4) & 1) * 8;
    const int b_kb = (lane >> 3) & 1;

    float acc[4][4][4];
    #pragma unroll
    for (int im = 0; im < 4; im++)
        #pragma unroll
        for (int jn = 0; jn < 4; jn++)
            #pragma unroll
            for (int c = 0; c < 4; c++) acc[im][jn][c] = 0.0f;

    g_load_stage(smb,             pA, pB, t, 0);
    g_load_stage(smb + STG_B,     pA, pB, t, 1);
    g_load_stage(smb + 2 * STG_B, pA, pB, t, 2);

    int buf = 0;
    #pragma unroll 1
    for (int s = 0; s < 16; s++) {
        if (s < 14)       asm volatile("cp.async.wait_group 2;" ::: "memory");
        else if (s == 14) asm volatile("cp.async.wait_group 1;" ::: "memory");
        else              asm volatile("cp.async.wait_group 0;" ::: "memory");
        __syncthreads();

        const uint32_t sb = smb + buf * STG_B;
        #pragma unroll
        for (int kk = 0; kk < 4; kk++) {
            const uint32_t k0 = kk * 16;
            uint32_t a[4][4], b[2][4];
            const uint32_t aoff = (warp_m + a_m) * 144 + (k0 + a_kb * 8) * 2;
            #pragma unroll
            for (int im = 0; im < 4; im++)
                LDSM4(a[im], sb + aoff + im * (16 * 144));
            #pragma unroll
            for (int j2 = 0; j2 < 2; j2++) {
                const uint32_t boff = (warp_n + j2 * 16 + b_n) * 144 + (k0 + b_kb * 8) * 2;
                LDSM4(b[j2], sb + AST + boff);
            }
            #pragma unroll
            for (int im = 0; im < 4; im++)
                #pragma unroll
                for (int jn = 0; jn < 4; jn++) {
                    const int j2 = jn >> 1, jr = (jn & 1) * 2;
                    MMAF16(acc[im][jn], a[im], b[j2][jr], b[j2][jr + 1]);
                }
        }
        __syncthreads();
        if (s + 3 < 16) g_load_stage(sb, pA, pB, t, s + 3);
        buf = (buf == 2) ? 0 : buf + 1;
    }

    const int r0 = lane >> 2, c0 = (lane & 3) * 2;
    #pragma unroll
    for (int im = 0; im < 4; im++)
        #pragma unroll
        for (int jn = 0; jn < 4; jn++) {
            const int row = m0 + warp_m + im * 16 + r0;
            const int col = nb + warp_n + jn * 8 + c0;
            if constexpr (sizeof(TO) == 2) {
                *(__half2*)&C[(size_t)row * ldc + col] =
                    __floats2half2_rn(acc[im][jn][0], acc[im][jn][1]);
                *(__half2*)&C[(size_t)(row + 8) * ldc + col] =
                    __floats2half2_rn(acc[im][jn][2], acc[im][jn][3]);
            } else {
                *(float2*)&C[(size_t)row * ldc + col] =
                    make_float2(acc[im][jn][0], acc[im][jn][1]);
                *(float2*)&C[(size_t)(row + 8) * ldc + col] =
                    make_float2(acc[im][jn][2], acc[im][jn][3]);
            }
        }
}

// -------- postprocess: q/k norm+rotary (by<5) and v-gate (by>=5), fp16 in ----
#define LOG2E 1.4426950408889634f
__global__ __launch_bounds__(128) void pp(const float* __restrict__ q_gain)
{
    const int m = blockIdx.x;
    const __half* row = g_qkvg + (size_t)m * NTOT;

    if (blockIdx.y >= 5) {
        const int i = (blockIdx.y - 5) * 128 + threadIdx.x;
        float v = __half2float(row[1280 + i]);
        float g = __half2float(row[1536 + i]);
        float vg = v / (1.0f + __expf(-g));
        int kvh = i >> 6, d = i & 63, hf = d >> 5, dc = d & 31;
        size_t o = ((size_t)(kvh * 2 + hf) * S_LEN + m) * 32 + dc;
        g_av[o] = __float2half_rn(vg);
        return;
    }

    const int w = threadIdx.x >> 5, l = threadIdx.x & 31;
    const int unit = blockIdx.y * 4 + w;
    const bool isq = unit < 16;
    const int h = isq ? unit : unit - 16;
    const int col0 = isq ? h * HD : 1024 + h * HD;
    float x1 = __half2float(row[col0 + l]);
    float x2 = __half2float(row[col0 + l + 32]);
    float ss = x1 * x1 + x2 * x2;
    #pragma unroll
    for (int o = 16; o > 0; o >>= 1) ss += __shfl_xor_sync(0xffffffffu, ss, o);
    const float rn = rsqrtf(ss * (1.0f / 64.0f) + 1.1920929e-7f);
    x1 *= rn; x2 *= rn;
    const float2 rc = g_rot[m * 32 + l];
    float y0 = x1 * rc.x + x2 * rc.y;
    float y1 = -x1 * rc.y + x2 * rc.x;
    const size_t o0 = ((size_t)(h * 2 + 0) * S_LEN + m) * 32 + l;
    const size_t o1 = ((size_t)(h * 2 + 1) * S_LEN + m) * 32 + l;
    if (isq) {
        const float gs = q_gain[h] * (0.17677669529663688f * LOG2E);
        g_aq[o0] = __float2half_rn(y0 * gs);
        g_aq[o1] = __float2half_rn(y1 * gs);
    } else {
        g_ak[o0] = __float2half_rn(y0);
        g_ak[o1] = __float2half_rn(y1);
    }
}

// -------- HMMA flash attention (unchanged from R12) --------
#define ATILE 5120
#define QTILE 5120
#define KVST  (4 * ATILE)
#define ASMEM (2 * KVST + 2 * QTILE)   // 51200

__device__ __forceinline__ void a_load_kv(
    uint32_t sb, const char* k0, const char* v0,
    const char* k1, const char* v1, int t, int key0)
{
    #pragma unroll
    for (int j = 0; j < 8; j++) {
        const int c = t + 128 * j;
        const int arr = c >> 8, rem = c & 255;
        const int row = rem >> 2, c4 = rem & 3;
        const char* src = (arr == 0) ? k0 : (arr == 1) ? v0 : (arr == 2) ? k1 : v1;
        CP16(sb + arr * ATILE + row * 80 + c4 * 16,
             src + ((size_t)(key0 + row) * 32 + c4 * 8) * 2);
    }
    asm volatile("cp.async.commit_group;" ::: "memory");
}

__global__ __launch_bounds__(128, 3) void attn_mma(const float* __restrict__ lambda_p)
{
    extern __shared__ char sm[];
    const int qt = gridDim.x - 1 - blockIdx.x;
    const int h = blockIdx.y, kvh = h >> 2;
    const int t = threadIdx.x, w = t >> 5, l = t & 31;
    const int q0 = qt * 64;
    const uint32_t smb = smem_u32(sm);
    const uint32_t sQ = smb + 2 * KVST;

    const char* q_g0 = (const char*)(g_aq + ((size_t)(h * 2 + 0) * S_LEN + q0) * 32);
    const char* q_g1 = (const char*)(g_aq + ((size_t)(h * 2 + 1) * S_LEN + q0) * 32);
    const char* k_g0 = (const char*)(g_ak + (size_t)(kvh * 2 + 0) * S_LEN * 32);
    const char* k_g1 = (const char*)(g_ak + (size_t)(kvh * 2 + 1) * S_LEN * 32);
    const char* v_g0 = (const char*)(g_av + (size_t)(kvh * 2 + 0) * S_LEN * 32);
    const char* v_g1 = (const char*)(g_av + (size_t)(kvh * 2 + 1) * S_LEN * 32);

    #pragma unroll
    for (int j = 0; j < 4; j++) {
        const int c = t + 128 * j;
        const int half = c >> 8, rem = c & 255;
        const int row = rem >> 2, c4 = rem & 3;
        CP16(sQ + half * QTILE + row * 80 + c4 * 16,
             (half ? q_g1 : q_g0) + ((size_t)row * 32 + c4 * 8) * 2);
    }
    a_load_kv(smb, k_g0, v_g0, k_g1, v_g1, t, 0);
    const int nt = qt + 1;
    if (nt > 1) a_load_kv(smb + KVST, k_g0, v_g0, k_g1, v_g1, t, 64);

    uint32_t qf[2][2][4];
    float O[2][4][4];
    #pragma unroll
    for (int hf = 0; hf < 2; hf++)
        #pragma unroll
        for (int nd = 0; nd < 4; nd++)
            #pragma unroll
            for (int c = 0; c < 4; c++) O[hf][nd][c] = 0.0f;
    float lp[2][2] = {{0.0f, 0.0f}, {0.0f, 0.0f}};

    const int row0 = q0 + w * 16 + (l >> 2);
    const int qmax_w = q0 + w * 16 + 15;
    const int qmin_w = q0 + w * 16;

    #pragma unroll 1
    for (int i = 0; i < nt; i++) {
        if (i + 1 < nt) asm volatile("cp.async.wait_group 1;" ::: "memory");
        else            asm volatile("cp.async.wait_group 0;" ::: "memory");
        __syncthreads();

        if (i == 0) {
            const uint32_t qoff = (w * 16 + (l & 15)) * 80 + ((l >> 4) * 8) * 2;
            #pragma unroll
            for (int hf = 0; hf < 2; hf++) {
                LDSM4(qf[hf][0], sQ + hf * QTILE + qoff);
                LDSM4(qf[hf][1], sQ + hf * QTILE + qoff + 32);
            }
        }

        const uint32_t sb = smb + (i & 1) * KVST;
        const int key0 = i * 64;

        if (key0 <= qmax_w) {
            const bool diag = (key0 + 63 > qmin_w);
            #pragma unroll
            for (int hf = 0; hf < 2; hf++) {
                const uint32_t skv = sb + hf * 2 * ATILE;
                float s[8][4];
                #pragma unroll
                for (int n = 0; n < 8; n++)
                    #pragma unroll
                    for (int c = 0; c < 4; c++) s[n][c] = 0.0f;

                #pragma unroll
                for (int ks = 0; ks < 2; ks++) {
                    #pragma unroll
                    for (int g = 0; g < 4; g++) {
                        uint32_t kf[4];
                        const uint32_t ka = skv
                            + (g * 16 + (l & 7) + ((l >> 4) & 1) * 8) * 80
                            + (ks * 16 + ((l >> 3) & 1) * 8) * 2;
                        LDSM4(kf, ka);
                        MMAF16(s[2*g],   qf[hf][ks], kf[0], kf[1]);
                        MMAF16(s[2*g+1], qf[hf][ks], kf[2], kf[3]);
                    }
                }

                if (diag) {
                    #pragma unroll
                    for (int n = 0; n < 8; n++) {
                        const int cb = key0 + n * 8 + (l & 3) * 2;
                        if (cb     > row0)     s[n][0] = -1e30f;
                        if (cb + 1 > row0)     s[n][1] = -1e30f;
                        if (cb     > row0 + 8) s[n][2] = -1e30f;
                        if (cb + 1 > row0 + 8) s[n][3] = -1e30f;
                    }
                }

                uint32_t aP[4][4];
                #pragma unroll
                for (int j = 0; j < 4; j++) {
                    #pragma unroll
                    for (int q = 0; q < 2; q++) {
                        const int n = 2 * j + q;
                        float p0, p1, p2, p3;
                        EX2(p0, s[n][0]);
                        EX2(p1, s[n][1]);
                        EX2(p2, s[n][2]);
                        EX2(p3, s[n][3]);
                        lp[hf][0] += p0 + p1;
                        lp[hf][1] += p2 + p3;
                        PACKF16(aP[j][2*q],     p0, p1);
                        PACKF16(aP[j][2*q + 1], p2, p3);
                    }
                }

                #pragma unroll
                for (int j = 0; j < 4; j++) {
                    #pragma unroll
                    for (int dg = 0; dg < 2; dg++) {
                        uint32_t vf[4];
                        const uint32_t va = skv + ATILE
                            + (16 * j + (l & 7) + ((l >> 3) & 1) * 8) * 80
                            + (dg * 16 + ((l >> 4) & 1) * 8) * 2;
                        LDSM4T(vf, va);
                        MMAF16(O[hf][2*dg],     aP[j], vf[0], vf[1]);
                        MMAF16(O[hf][2*dg + 1], aP[j], vf[2], vf[3]);
                    }
                }
            }
        }

        __syncthreads();
        if (i + 2 < nt)
            a_load_kv(sb, k_g0, v_g0, k_g1, v_g1, t, (i + 2) * 64);
    }

    #pragma unroll
    for (int hf = 0; hf < 2; hf++)
        #pragma unroll
        for (int r = 0; r < 2; r++) {
            lp[hf][r] += __shfl_xor_sync(0xffffffffu, lp[hf][r], 1);
            lp[hf][r] += __shfl_xor_sync(0xffffffffu, lp[hf][r], 2);
        }
    const float inv00 = 1.0f / lp[0][0], inv01 = 1.0f / lp[0][1];
    const float inv10 = 1.0f / lp[1][0], inv11 = 1.0f / lp[1][1];
    const float lam = lambda_p[h];

    #pragma unroll
    for (int nd = 0; nd < 4; nd++) {
        const int col = nd * 8 + (l & 3) * 2;
        #pragma unroll
        for (int r = 0; r < 2; r++) {
            const int m = row0 + r * 8;
            const float i0 = r ? inv01 : inv00;
            const float i1 = r ? inv11 : inv10;
            const float a1a = O[0][nd][2*r]     * i0;
            const float a1b = O[0][nd][2*r + 1] * i0;
            const float a2a = O[1][nd][2*r]     * i1;
            const float a2b = O[1][nd][2*r + 1] * i1;
            __half* yp = g_yh + (size_t)m * DIM + h * HD + col;
            *(__half2*)yp        = __floats2half2_rn(a1a - lam * a2a, a1b - lam * a2b);
            *(__half2*)(yp + 32) = __floats2half2_rn(a1a + lam * a2a, a1b + lam * a2b);
        }
    }
}

extern "C" void kernel_launch(void* const* d_in, const int* in_sizes, int n_in,
                              void* d_out, int out_size)
{
    const float* x        = (const float*)d_in[0];
    const float* Wq       = (const float*)d_in[1];
    const float* Wk       = (const float*)d_in[2];
    const float* Wv       = (const float*)d_in[3];
    const float* Wg       = (const float*)d_in[4];
    const float* Wo       = (const float*)d_in[5];
    const float* q_gain   = (const float*)d_in[6];
    const float* lambda_p = (const float*)d_in[7];
    float* out = (float*)d_out;

    cudaFuncSetAttribute(gemm_f16<__half>, cudaFuncAttributeMaxDynamicSharedMemorySize, GSMEM);
    cudaFuncSetAttribute(gemm_f16<float>,  cudaFuncAttributeMaxDynamicSharedMemorySize, GSMEM);
    cudaFuncSetAttribute(attn_mma, cudaFuncAttributeMaxDynamicSharedMemorySize, ASMEM);

    __half *qkvg_p, *xh, *wh, *woh, *yh;
    cudaGetSymbolAddress((void**)&qkvg_p, g_qkvg);
    cudaGetSymbolAddress((void**)&xh, g_xh);
    cudaGetSymbolAddress((void**)&wh, g_wh);
    cudaGetSymbolAddress((void**)&woh, g_woh);
    cudaGetSymbolAddress((void**)&yh, g_yh);

    conv_all<<<2688, 256>>>(x, Wq, Wk, Wv, Wg, Wo);
    gemm_f16<__half><<<dim3(NTOT/128, S_LEN/128), 256, GSMEM>>>(xh, wh, qkvg_p, NTOT);
    pp<<<dim3(S_LEN, 7), 128>>>(q_gain);
    attn_mma<<<dim3(S_LEN/64, NH), 128, ASMEM>>>(lambda_p);
    gemm_f16<float><<<dim3(DIM/128, S_LEN/128), 256, GSMEM>>>(yh, woh, out, DIM);
}

// round 14
// speedup vs baseline: 1.1240x; 1.0190x over previous
#include <cuda_runtime.h>
#include <cuda_bf16.h>
#include <cuda_fp16.h>
#include <math.h>
#include <stdint.h>

#define S_LEN 2048
#define DIM 1024
#define NH 16
#define KVH 4
#define HD 64
#define NTOT 1792

__device__ __half g_qkvg[S_LEN * NTOT];
__device__ float2 g_rot[S_LEN * 32];
__device__ __half g_xh[S_LEN * DIM];
__device__ __half g_wh[NTOT * DIM];
__device__ __half g_woh[DIM * DIM];
__device__ __half g_yh[S_LEN * DIM];
__device__ __half g_aq[NH*2*S_LEN*32];
__device__ __half g_ak[KVH*2*S_LEN*32];
__device__ __half g_av[KVH*2*S_LEN*32];

__device__ __forceinline__ uint32_t smem_u32(const void* p) {
    uint32_t a;
    asm("{ .reg .u64 t; cvta.to.shared.u64 t, %1; cvt.u32.u64 %0, t; }" : "=r"(a) : "l"(p));
    return a;
}
#define CP16(sm, gp) asm volatile("cp.async.cg.shared.global [%0], [%1], 16;" :: "r"(sm), "l"(gp))
#define LDSM4(r, addr) \
    asm volatile("ldmatrix.sync.aligned.m8n8.x4.shared.b16 {%0,%1,%2,%3}, [%4];" \
        : "=r"((r)[0]), "=r"((r)[1]), "=r"((r)[2]), "=r"((r)[3]) : "r"(addr))
#define LDSM4T(r, addr) \
    asm volatile("ldmatrix.sync.aligned.m8n8.x4.trans.shared.b16 {%0,%1,%2,%3}, [%4];" \
        : "=r"((r)[0]), "=r"((r)[1]), "=r"((r)[2]), "=r"((r)[3]) : "r"(addr))
#define MMAF16(d, a, b0, b1) \
    asm volatile("mma.sync.aligned.m16n8k16.row.col.f32.f16.f16.f32 " \
        "{%0,%1,%2,%3}, {%4,%5,%6,%7}, {%8,%9}, {%0,%1,%2,%3};" \
        : "+f"((d)[0]), "+f"((d)[1]), "+f"((d)[2]), "+f"((d)[3]) \
        : "r"((a)[0]), "r"((a)[1]), "r"((a)[2]), "r"((a)[3]), "r"(b0), "r"(b1))
#define PACKF16(r, a, b) asm("cvt.rn.f16x2.f32 %0, %1, %2;" : "=r"(r) : "f"(b), "f"(a))
#define EX2(d, x) asm("ex2.approx.ftz.f32 %0, %1;" : "=f"(d) : "f"(x))

// -------- conversion: one float4 -> fp16x4 --------
__device__ __forceinline__ void conv_one(
    int i, const float* __restrict__ x,  const float* __restrict__ Wq,
    const float* __restrict__ Wk, const float* __restrict__ Wv,
    const float* __restrict__ Wg, const float* __restrict__ Wo)
{
    const float* s; __half* d;
    if (i < 524288)      { size_t j = (size_t)i * 4;            s = x  + j; d = g_xh + j; }
    else if (i < 786432) { size_t j = (size_t)(i - 524288) * 4; s = Wq + j; d = g_wh + j; }
    else if (i < 851968) { size_t j = (size_t)(i - 786432) * 4; s = Wk + j; d = g_wh + 1048576 + j; }
    else if (i < 917504) { size_t j = (size_t)(i - 851968) * 4; s = Wv + j; d = g_wh + 1310720 + j; }
    else if (i < 983040) { size_t j = (size_t)(i - 917504) * 4; s = Wg + j; d = g_wh + 1572864 + j; }
    else                 { size_t j = (size_t)(i - 983040) * 4; s = Wo + j; d = g_woh + j; }
    float4 v = *(const float4*)s;
    *(__half2*)d       = __floats2half2_rn(v.x, v.y);
    *(__half2*)(d + 2) = __floats2half2_rn(v.z, v.w);
}

__global__ __launch_bounds__(256) void conv_all(
    const float* __restrict__ x,  const float* __restrict__ Wq,
    const float* __restrict__ Wk, const float* __restrict__ Wv,
    const float* __restrict__ Wg, const float* __restrict__ Wo)
{
    if (blockIdx.x >= 2432) {
        const int i = (blockIdx.x - 2432) * 256 + threadIdx.x;
        const int m = i >> 5, t = i & 31;
        const float angle = ((float)(2 * t) / 64.0f) * 3.14159274101257324f;
        const float ang = (float)m * angle;
        double a = (double)ang;
        a -= rint(a * 0.15915494309189535) * 6.283185307179586;
        float c, sn;
        sincosf((float)a, &sn, &c);
        const float radius = 1.0f / (1.0f + (float)m * 0.01f);
        g_rot[i] = make_float2(c * radius, sn * radius);
        return;
    }
    const int i = blockIdx.x * 256 + threadIdx.x;
    conv_one(i,          x, Wq, Wk, Wv, Wg, Wo);
    conv_one(i + 622592, x, Wq, Wk, Wv, Wg, Wo);
}

// -------- fp16 HMMA GEMM, 3-stage, forced 2 CTAs/SM --------
#define AST   18432
#define STG_B (2 * AST)
#define GSMEM (3 * STG_B)           // 110592

__device__ __forceinline__ void g_load_stage(
    uint32_t sb, const char* pA, const char* pB, int t, int s)
{
    const size_t gk = (size_t)s * 128;
    #pragma unroll
    for (int j = 0; j < 8; j++) {
        const int idx = t + 256 * j;
        const int arr = idx >> 10, rem = idx & 1023;
        const int row = rem >> 3, kc = rem & 7;
        const size_t go = (size_t)row * 2048 + gk + kc * 16;
        const uint32_t so = arr * AST + row * 144 + kc * 16;
        CP16(sb + so, (arr ? pB : pA) + go);
    }
    asm volatile("cp.async.commit_group;" ::: "memory");
}

template <typename TO>
__global__ __launch_bounds__(256, 2) void gemm_f16(
    const __half* __restrict__ A, const __half* __restrict__ B,
    TO* __restrict__ C, int ldc)
{
    extern __shared__ char sm[];
    const int t = threadIdx.x, wid = t >> 5, lane = t & 31;
    const int m0 = blockIdx.y * 128, nb = blockIdx.x * 128;
    const uint32_t smb = smem_u32(sm);

    const char* pA = (const char*)A + (size_t)m0 * 2048;
    const char* pB = (const char*)B + (size_t)nb * 2048;

    const int warp_m = (wid & 1) * 64;
    const int warp_n = (wid >> 1) * 32;
    const int a_m  = lane & 15;
    const int a_kb = lane >> 4;
    const int b_n  = (lane & 7) + ((lane >> 4) & 1) * 8;
    const int b_kb = (lane >> 3) & 1;

    float acc[4][4][4];
    #pragma unroll
    for (int im = 0; im < 4; im++)
        #pragma unroll
        for (int jn = 0; jn < 4; jn++)
            #pragma unroll
            for (int c = 0; c < 4; c++) acc[im][jn][c] = 0.0f;

    g_load_stage(smb,             pA, pB, t, 0);
    g_load_stage(smb + STG_B,     pA, pB, t, 1);
    g_load_stage(smb + 2 * STG_B, pA, pB, t, 2);

    int buf = 0;
    #pragma unroll 1
    for (int s = 0; s < 16; s++) {
        if (s < 14)       asm volatile("cp.async.wait_group 2;" ::: "memory");
        else if (s == 14) asm volatile("cp.async.wait_group 1;" ::: "memory");
        else              asm volatile("cp.async.wait_group 0;" ::: "memory");
        __syncthreads();

        const uint32_t sb = smb + buf * STG_B;
        #pragma unroll
        for (int kk = 0; kk < 4; kk++) {
            const uint32_t k0 = kk * 16;
            uint32_t a[4][4], b[2][4];
            const uint32_t aoff = (warp_m + a_m) * 144 + (k0 + a_kb * 8) * 2;
            #pragma unroll
            for (int im = 0; im < 4; im++)
                LDSM4(a[im], sb + aoff + im * (16 * 144));
            #pragma unroll
            for (int j2 = 0; j2 < 2; j2++) {
                const uint32_t boff = (warp_n + j2 * 16 + b_n) * 144 + (k0 + b_kb * 8) * 2;
                LDSM4(b[j2], sb + AST + boff);
            }
            #pragma unroll
            for (int im = 0; im < 4; im++)
                #pragma unroll
                for (int jn = 0; jn < 4; jn++) {
                    const int j2 = jn >> 1, jr = (jn & 1) * 2;
                    MMAF16(acc[im][jn], a[im], b[j2][jr], b[j2][jr + 1]);
                }
        }
        __syncthreads();
        if (s + 3 < 16) g_load_stage(sb, pA, pB, t, s + 3);
        buf = (buf == 2) ? 0 : buf + 1;
    }

    const int r0 = lane >> 2, c0 = (lane & 3) * 2;
    #pragma unroll
    for (int im = 0; im < 4; im++)
        #pragma unroll
        for (int jn = 0; jn < 4; jn++) {
            const int row = m0 + warp_m + im * 16 + r0;
            const int col = nb + warp_n + jn * 8 + c0;
            if constexpr (sizeof(TO) == 2) {
                *(__half2*)&C[(size_t)row * ldc + col] =
                    __floats2half2_rn(acc[im][jn][0], acc[im][jn][1]);
                *(__half2*)&C[(size_t)(row + 8) * ldc + col] =
                    __floats2half2_rn(acc[im][jn][2], acc[im][jn][3]);
            } else {
                *(float2*)&C[(size_t)row * ldc + col] =
                    make_float2(acc[im][jn][0], acc[im][jn][1]);
                *(float2*)&C[(size_t)(row + 8) * ldc + col] =
                    make_float2(acc[im][jn][2], acc[im][jn][3]);
            }
        }
}

// -------- postprocess --------
#define LOG2E 1.4426950408889634f
__global__ __launch_bounds__(128) void pp(const float* __restrict__ q_gain)
{
    const int m = blockIdx.x;
    const __half* row = g_qkvg + (size_t)m * NTOT;

    if (blockIdx.y >= 5) {
        const int i = (blockIdx.y - 5) * 128 + threadIdx.x;
        float v = __half2float(row[1280 + i]);
        float g = __half2float(row[1536 + i]);
        float vg = v / (1.0f + __expf(-g));
        int kvh = i >> 6, d = i & 63, hf = d >> 5, dc = d & 31;
        size_t o = ((size_t)(kvh * 2 + hf) * S_LEN + m) * 32 + dc;
        g_av[o] = __float2half_rn(vg);
        return;
    }

    const int w = threadIdx.x >> 5, l = threadIdx.x & 31;
    const int unit = blockIdx.y * 4 + w;
    const bool isq = unit < 16;
    const int h = isq ? unit : unit - 16;
    const int col0 = isq ? h * HD : 1024 + h * HD;
    float x1 = __half2float(row[col0 + l]);
    float x2 = __half2float(row[col0 + l + 32]);
    float ss = x1 * x1 + x2 * x2;
    #pragma unroll
    for (int o = 16; o > 0; o >>= 1) ss += __shfl_xor_sync(0xffffffffu, ss, o);
    const float rn = rsqrtf(ss * (1.0f / 64.0f) + 1.1920929e-7f);
    x1 *= rn; x2 *= rn;
    const float2 rc = g_rot[m * 32 + l];
    float y0 = x1 * rc.x + x2 * rc.y;
    float y1 = -x1 * rc.y + x2 * rc.x;
    const size_t o0 = ((size_t)(h * 2 + 0) * S_LEN + m) * 32 + l;
    const size_t o1 = ((size_t)(h * 2 + 1) * S_LEN + m) * 32 + l;
    if (isq) {
        const float gs = q_gain[h] * (0.17677669529663688f * LOG2E);
        g_aq[o0] = __float2half_rn(y0 * gs);
        g_aq[o1] = __float2half_rn(y1 * gs);
    } else {
        g_ak[o0] = __float2half_rn(y0);
        g_ak[o1] = __float2half_rn(y1);
    }
}

// -------- HMMA flash attention: lp via ones-MMA --------
#define ATILE 5120
#define QTILE 5120
#define KVST  (4 * ATILE)
#define ASMEM (2 * KVST + 2 * QTILE)   // 51200
#define ONES16 0x3C003C00u             // fp16 {1.0, 1.0}

__device__ __forceinline__ void a_load_kv(
    uint32_t sb, const char* k0, const char* v0,
    const char* k1, const char* v1, int t, int key0)
{
    #pragma unroll
    for (int j = 0; j < 8; j++) {
        const int c = t + 128 * j;
        const int arr = c >> 8, rem = c & 255;
        const int row = rem >> 2, c4 = rem & 3;
        const char* src = (arr == 0) ? k0 : (arr == 1) ? v0 : (arr == 2) ? k1 : v1;
        CP16(sb + arr * ATILE + row * 80 + c4 * 16,
             src + ((size_t)(key0 + row) * 32 + c4 * 8) * 2);
    }
    asm volatile("cp.async.commit_group;" ::: "memory");
}

__global__ __launch_bounds__(128, 3) void attn_mma(const float* __restrict__ lambda_p)
{
    extern __shared__ char sm[];
    const int qt = gridDim.x - 1 - blockIdx.x;
    const int h = blockIdx.y, kvh = h >> 2;
    const int t = threadIdx.x, w = t >> 5, l = t & 31;
    const int q0 = qt * 64;
    const uint32_t smb = smem_u32(sm);
    const uint32_t sQ = smb + 2 * KVST;

    const char* q_g0 = (const char*)(g_aq + ((size_t)(h * 2 + 0) * S_LEN + q0) * 32);
    const char* q_g1 = (const char*)(g_aq + ((size_t)(h * 2 + 1) * S_LEN + q0) * 32);
    const char* k_g0 = (const char*)(g_ak + (size_t)(kvh * 2 + 0) * S_LEN * 32);
    const char* k_g1 = (const char*)(g_ak + (size_t)(kvh * 2 + 1) * S_LEN * 32);
    const char* v_g0 = (const char*)(g_av + (size_t)(kvh * 2 + 0) * S_LEN * 32);
    const char* v_g1 = (const char*)(g_av + (size_t)(kvh * 2 + 1) * S_LEN * 32);

    #pragma unroll
    for (int j = 0; j < 4; j++) {
        const int c = t + 128 * j;
        const int half = c >> 8, rem = c & 255;
        const int row = rem >> 2, c4 = rem & 3;
        CP16(sQ + half * QTILE + row * 80 + c4 * 16,
             (half ? q_g1 : q_g0) + ((size_t)row * 32 + c4 * 8) * 2);
    }
    a_load_kv(smb, k_g0, v_g0, k_g1, v_g1, t, 0);
    const int nt = qt + 1;
    if (nt > 1) a_load_kv(smb + KVST, k_g0, v_g0, k_g1, v_g1, t, 64);

    uint32_t qf[2][2][4];
    float O[2][4][4];
    float lpacc[2][4];                 // ones-MMA accumulator: row sums of P
    #pragma unroll
    for (int hf = 0; hf < 2; hf++) {
        #pragma unroll
        for (int nd = 0; nd < 4; nd++)
            #pragma unroll
            for (int c = 0; c < 4; c++) O[hf][nd][c] = 0.0f;
        #pragma unroll
        for (int c = 0; c < 4; c++) lpacc[hf][c] = 0.0f;
    }

    const int row0 = q0 + w * 16 + (l >> 2);
    const int qmax_w = q0 + w * 16 + 15;
    const int qmin_w = q0 + w * 16;

    #pragma unroll 1
    for (int i = 0; i < nt; i++) {
        if (i + 1 < nt) asm volatile("cp.async.wait_group 1;" ::: "memory");
        else            asm volatile("cp.async.wait_group 0;" ::: "memory");
        __syncthreads();

        if (i == 0) {
            const uint32_t qoff = (w * 16 + (l & 15)) * 80 + ((l >> 4) * 8) * 2;
            #pragma unroll
            for (int hf = 0; hf < 2; hf++) {
                LDSM4(qf[hf][0], sQ + hf * QTILE + qoff);
                LDSM4(qf[hf][1], sQ + hf * QTILE + qoff + 32);
            }
        }

        const uint32_t sb = smb + (i & 1) * KVST;
        const int key0 = i * 64;

        if (key0 <= qmax_w) {
            const bool diag = (key0 + 63 > qmin_w);
            #pragma unroll
            for (int hf = 0; hf < 2; hf++) {
                const uint32_t skv = sb + hf * 2 * ATILE;
                float s[8][4];
                #pragma unroll
                for (int n = 0; n < 8; n++)
                    #pragma unroll
                    for (int c = 0; c < 4; c++) s[n][c] = 0.0f;

                #pragma unroll
                for (int ks = 0; ks < 2; ks++) {
                    #pragma unroll
                    for (int g = 0; g < 4; g++) {
                        uint32_t kf[4];
                        const uint32_t ka = skv
                            + (g * 16 + (l & 7) + ((l >> 4) & 1) * 8) * 80
                            + (ks * 16 + ((l >> 3) & 1) * 8) * 2;
                        LDSM4(kf, ka);
                        MMAF16(s[2*g],   qf[hf][ks], kf[0], kf[1]);
                        MMAF16(s[2*g+1], qf[hf][ks], kf[2], kf[3]);
                    }
                }

                if (diag) {
                    #pragma unroll
                    for (int n = 0; n < 8; n++) {
                        const int cb = key0 + n * 8 + (l & 3) * 2;
                        if (cb     > row0)     s[n][0] = -1e30f;
                        if (cb + 1 > row0)     s[n][1] = -1e30f;
                        if (cb     > row0 + 8) s[n][2] = -1e30f;
                        if (cb + 1 > row0 + 8) s[n][3] = -1e30f;
                    }
                }

                uint32_t aP[4][4];
                #pragma unroll
                for (int j = 0; j < 4; j++) {
                    #pragma unroll
                    for (int q = 0; q < 2; q++) {
                        const int n = 2 * j + q;
                        float p0, p1, p2, p3;
                        EX2(p0, s[n][0]);
                        EX2(p1, s[n][1]);
                        EX2(p2, s[n][2]);
                        EX2(p3, s[n][3]);
                        PACKF16(aP[j][2*q],     p0, p1);
                        PACKF16(aP[j][2*q + 1], p2, p3);
                    }
                }

                #pragma unroll
                for (int j = 0; j < 4; j++) {
                    // lp row-sum via ones-MMA (all 8 columns = full row sum)
                    MMAF16(lpacc[hf], aP[j], ONES16, ONES16);
                    #pragma unroll
                    for (int dg = 0; dg < 2; dg++) {
                        uint32_t vf[4];
                        const uint32_t va = skv + ATILE
                            + (16 * j + (l & 7) + ((l >> 3) & 1) * 8) * 80
                            + (dg * 16 + ((l >> 4) & 1) * 8) * 2;
                        LDSM4T(vf, va);
                        MMAF16(O[hf][2*dg],     aP[j], vf[0], vf[1]);
                        MMAF16(O[hf][2*dg + 1], aP[j], vf[2], vf[3]);
                    }
                }
            }
        }

        __syncthreads();
        if (i + 2 < nt)
            a_load_kv(sb, k_g0, v_g0, k_g1, v_g1, t, (i + 2) * 64);
    }

    // lpacc[hf][0] = full row sum for row0; lpacc[hf][2] = row0+8 (no shfl needed)
    const float inv00 = 1.0f / lpacc[0][0], inv01 = 1.0f / lpacc[0][2];
    const float inv10 = 1.0f / lpacc[1][0], inv11 = 1.0f / lpacc[1][2];
    const float lam = lambda_p[h];

    #pragma unroll
    for (int nd = 0; nd < 4; nd++) {
        const int col = nd * 8 + (l & 3) * 2;
        #pragma unroll
        for (int r = 0; r < 2; r++) {
            const int m = row0 + r * 8;
            const float i0 = r ? inv01 : inv00;
            const float i1 = r ? inv11 : inv10;
            const float a1a = O[0][nd][2*r]     * i0;
            const float a1b = O[0][nd][2*r + 1] * i0;
            const float a2a = O[1][nd][2*r]     * i1;
            const float a2b = O[1][nd][2*r + 1] * i1;
            __half* yp = g_yh + (size_t)m * DIM + h * HD + col;
            *(__half2*)yp        = __floats2half2_rn(a1a - lam * a2a, a1b - lam * a2b);
            *(__half2*)(yp + 32) = __floats2half2_rn(a1a + lam * a2a, a1b + lam * a2b);
        }
    }
}

extern "C" void kernel_launch(void* const* d_in, const int* in_sizes, int n_in,
                              void* d_out, int out_size)
{
    const float* x        = (const float*)d_in[0];
    const float* Wq       = (const float*)d_in[1];
    const float* Wk       = (const float*)d_in[2];
    const float* Wv       = (const float*)d_in[3];
    const float* Wg       = (const float*)d_in[4];
    const float* Wo       = (const float*)d_in[5];
    const float* q_gain   = (const float*)d_in[6];
    const float* lambda_p = (const float*)d_in[7];
    float* out = (float*)d_out;

    cudaFuncSetAttribute(gemm_f16<__half>, cudaFuncAttributeMaxDynamicSharedMemorySize, GSMEM);
    cudaFuncSetAttribute(gemm_f16<float>,  cudaFuncAttributeMaxDynamicSharedMemorySize, GSMEM);
    cudaFuncSetAttribute(attn_mma, cudaFuncAttributeMaxDynamicSharedMemorySize, ASMEM);

    __half *qkvg_p, *xh, *wh, *woh, *yh;
    cudaGetSymbolAddress((void**)&qkvg_p, g_qkvg);
    cudaGetSymbolAddress((void**)&xh, g_xh);
    cudaGetSymbolAddress((void**)&wh, g_wh);
    cudaGetSymbolAddress((void**)&woh, g_woh);
    cudaGetSymbolAddress((void**)&yh, g_yh);

    conv_all<<<2688, 256>>>(x, Wq, Wk, Wv, Wg, Wo);
    gemm_f16<__half><<<dim3(NTOT/128, S_LEN/128), 256, GSMEM>>>(xh, wh, qkvg_p, NTOT);
    pp<<<dim3(S_LEN, 7), 128>>>(q_gain);
    attn_mma<<<dim3(S_LEN/64, NH), 128, ASMEM>>>(lambda_p);
    gemm_f16<float><<<dim3(DIM/128, S_LEN/128), 256, GSMEM>>>(yh, woh, out, DIM);
}